// round 16
// baseline (speedup 1.0000x reference)
#include <cuda_runtime.h>
#include <cstdint>

#define NN      50000
#define NPADT   1564           /* 32-row tiles: 50048/32 */
#define NPAD    (NPADT*32)     /* 50048 */
#define HIDC    128
#define INC     256
#define LAYERS  3
#define NBINS   (NPAD*8)       /* 400384 */
#define EMAX    600000
#define SWA     20             /* smem row width in u32 (16 data + 4 pad) */

// ---------------- device scratch (static globals; no allocation) ----------------
__device__ __align__(16) float    g_hidden[(size_t)NPAD * 128];
__device__ __align__(16) float    g_cur[(size_t)NPAD * 128];       // fp32 for agg gather
__device__ __align__(16) uint32_t g_curhi[(size_t)NPAD * 64];      // packed bf16x2
__device__ __align__(16) uint32_t g_curlo[(size_t)NPAD * 64];
__device__ __align__(16) uint32_t g_agghi[(size_t)NPAD * 448];     // 896 k -> 448 pairs
__device__ __align__(16) uint32_t g_agglo[(size_t)NPAD * 448];
__device__ __align__(16) uint32_t g_xhi[(size_t)NPAD * 128];       // x pre-split (256 k)
__device__ __align__(16) uint32_t g_xlo[(size_t)NPAD * 128];
__device__ __align__(16) uint32_t g_whi[LAYERS * 128 * 512];       // [l][f][pc]
__device__ __align__(16) uint32_t g_wlo[LAYERS * 128 * 512];
__device__ __align__(16) uint32_t g_l1hi[128 * 128];               // [f][pc]
__device__ __align__(16) uint32_t g_l1lo[128 * 128];
__device__ int g_cnt[NBINS];
__device__ int g_off[NBINS];
__device__ int g_cursor[NBINS];
__device__ int g_bsum[NBINS / 1024];
__device__ int g_bsumx[NBINS / 1024];
__device__ int g_esrc[EMAX];

// ---------------- helpers ----------------
__device__ __forceinline__ uint32_t smem_u32p(const void* p) {
    uint32_t a;
    asm("{ .reg .u64 t; cvta.to.shared.u64 t, %1; cvt.u32.u64 %0, t; }" : "=r"(a) : "l"(p));
    return a;
}
__device__ __forceinline__ void cp_async16(uint32_t saddr, const void* g) {
    asm volatile("cp.async.ca.shared.global [%0], [%1], 16;" :: "r"(saddr), "l"(g));
}
__device__ __forceinline__ void cp_async8(uint32_t saddr, const void* g) {
    asm volatile("cp.async.ca.shared.global [%0], [%1], 8;" :: "r"(saddr), "l"(g));
}
__device__ __forceinline__ uint32_t pack2(float x, float y) {
    uint32_t r;
    asm("cvt.rn.bf16x2.f32 %0, %1, %2;" : "=r"(r) : "f"(y), "f"(x));
    return r;
}
__device__ __forceinline__ void split2(float x, float y, uint32_t& hi, uint32_t& lo) {
    hi = pack2(x, y);
    float fx = __uint_as_float(hi << 16);
    float fy = __uint_as_float(hi & 0xFFFF0000u);
    lo = pack2(x - fx, y - fy);
}
__device__ __forceinline__ void mma16816(float* d, const uint32_t* a, const uint32_t* b) {
    asm volatile(
        "mma.sync.aligned.m16n8k16.row.col.f32.bf16.bf16.f32 "
        "{%0,%1,%2,%3}, {%4,%5,%6,%7}, {%8,%9}, {%0,%1,%2,%3};"
        : "+f"(d[0]), "+f"(d[1]), "+f"(d[2]), "+f"(d[3])
        : "r"(a[0]), "r"(a[1]), "r"(a[2]), "r"(a[3]), "r"(b[0]), "r"(b[1]));
}

// ---------------- prep: conv weights packed bf16 hi/lo: [l][f][pc], k=2pc ----------
__global__ void conv_w_kernel(const float* __restrict__ comps,
                              const float* __restrict__ bases,
                              const float* __restrict__ roots) {
    int idx = blockIdx.x * blockDim.x + threadIdx.x;
    if (idx >= LAYERS * 128 * 512) return;
    int l   = idx / (128 * 512);
    int rem = idx % (128 * 512);
    int f   = rem >> 9;
    int pc  = rem & 511;
    int k0  = pc * 2;
    int r   = k0 >> 7, d = k0 & 127;
    float v0, v1;
    if (r < 7) {
        v0 = 0.f; v1 = 0.f;
#pragma unroll
        for (int b = 0; b < 8; b++) {
            float c = comps[l * 56 + r * 8 + b];
            const float* bb = bases + ((size_t)(l * 8 + b) * 128 + d) * 128 + f;
            v0 += c * bb[0];
            v1 += c * bb[128];
        }
    } else {
        const float* rr = roots + ((size_t)l * 128 + d) * 128 + f;
        v0 = rr[0];
        v1 = rr[128];
    }
    uint32_t hi, lo;
    split2(v0, v1, hi, lo);
    g_whi[idx] = hi;
    g_wlo[idx] = lo;
}

__global__ void l1_w_kernel(const float* __restrict__ w) {
    int idx = blockIdx.x * blockDim.x + threadIdx.x;
    if (idx >= 128 * 128) return;
    int f = idx >> 7, pc = idx & 127;
    int k0 = pc * 2;
    uint32_t hi, lo;
    split2(w[k0 * 128 + f], w[(k0 + 1) * 128 + f], hi, lo);
    g_l1hi[idx] = hi;
    g_l1lo[idx] = lo;
}

// ---------------- prep: x pre-split packed [node][128 pc] ----------------
__global__ void xsplit_kernel(const float* __restrict__ x, int M) {
    int idx = blockIdx.x * blockDim.x + threadIdx.x;
    if (idx >= NPAD * 128) return;
    int node = idx >> 7, pc = idx & 127;
    int k0 = pc * 2;
    float v0 = 0.f, v1 = 0.f;
    if (node < M) {
        v0 = x[(size_t)node * INC + k0];
        v1 = x[(size_t)node * INC + k0 + 1];
    }
    uint32_t hi, lo;
    split2(v0, v1, hi, lo);
    g_xhi[idx] = hi;
    g_xlo[idx] = lo;
}

// ---------------- counts / scan / sort ----------------
__global__ void zero_cnt_kernel() {
    int i = blockIdx.x * blockDim.x + threadIdx.x;
    if (i < NBINS) g_cnt[i] = 0;
}
__global__ void count_kernel(const int* __restrict__ dst, const int* __restrict__ et, int E) {
    int e = blockIdx.x * blockDim.x + threadIdx.x;
    if (e < E) atomicAdd(&g_cnt[dst[e] * 8 + et[e]], 1);
}
__global__ void scan1_kernel() {
    __shared__ int s[1024];
    int tid = threadIdx.x;
    int i   = blockIdx.x * 1024 + tid;
    int v   = g_cnt[i];
    s[tid] = v;
    __syncthreads();
#pragma unroll
    for (int o = 1; o < 1024; o <<= 1) {
        int t = (tid >= o) ? s[tid - o] : 0;
        __syncthreads();
        s[tid] += t;
        __syncthreads();
    }
    g_off[i] = s[tid] - v;
    if (tid == 1023) g_bsum[blockIdx.x] = s[1023];
}
__global__ void scan2_kernel() {
    __shared__ int s[512];
    int tid = threadIdx.x;
    int v = (tid < NBINS / 1024) ? g_bsum[tid] : 0;
    s[tid] = v;
    __syncthreads();
#pragma unroll
    for (int o = 1; o < 512; o <<= 1) {
        int t = (tid >= o) ? s[tid - o] : 0;
        __syncthreads();
        s[tid] += t;
        __syncthreads();
    }
    if (tid < NBINS / 1024) g_bsumx[tid] = s[tid] - v;
}
__global__ void scan3_kernel() {
    int i = blockIdx.x * blockDim.x + threadIdx.x;
    if (i >= NBINS) return;
    int o = g_off[i] + g_bsumx[i >> 10];
    g_off[i] = o;
    g_cursor[i] = o;
}
__global__ void sort_kernel(const int* __restrict__ src, const int* __restrict__ dst,
                            const int* __restrict__ et, int E) {
    int e = blockIdx.x * blockDim.x + threadIdx.x;
    if (e >= E) return;
    int key = dst[e] * 8 + et[e];
    int pos = atomicAdd(&g_cursor[key], 1);
    g_esrc[pos] = src[e];
}

// ---------------- aggregation (R10: warp per node, 7 descs preloaded) ----------
__global__ void agg_kernel(int M) {
    int t = blockIdx.x * blockDim.x + threadIdx.x;
    int d = t >> 5, lane = t & 31;
    if (d >= M) return;
    const float4* cur4 = (const float4*)g_cur;
    int st[7], n[7];
#pragma unroll
    for (int r = 0; r < 7; r++) {
        st[r] = __ldg(&g_off[d * 8 + r]);
        n[r]  = __ldg(&g_cnt[d * 8 + r]);
    }
#pragma unroll
    for (int r = 0; r < 7; r++) {
        float4 acc = make_float4(0.f, 0.f, 0.f, 0.f);
        for (int i = 0; i < n[r]; i++) {
            int s = __ldg(&g_esrc[st[r] + i]);
            float4 v = cur4[(size_t)s * 32 + lane];
            acc.x += v.x; acc.y += v.y; acc.z += v.z; acc.w += v.w;
        }
        float s = 1.f / fmaxf((float)n[r], 1.f);
        uint32_t h0, l0, h1, l1;
        split2(acc.x * s, acc.y * s, h0, l0);
        split2(acc.z * s, acc.w * s, h1, l1);
        size_t base = (size_t)d * 448 + r * 64;
        ((uint2*)(g_agghi + base))[lane] = make_uint2(h0, h1);
        ((uint2*)(g_agglo + base))[lane] = make_uint2(l0, l1);
    }
}

// ---------------- bf16x3 GEMM: 32x128 tile, K-tile 32, 2-stage pipeline, occ 3 ----
// NCH = number of 16-pc (32-k) chunks: conv 32 (28 agg + 4 cur), lin1 8.
// warp grid 1x8, warp tile m32 x n16, acc[2][2][4] = 16 regs/thread.
template <int NCH, int MODE>
__global__ void __launch_bounds__(256, 3) gemm_mma(
    const uint32_t* __restrict__ WH,
    const uint32_t* __restrict__ WL,
    const float* __restrict__ bias,
    const float* __restrict__ tempP,
    int relu, int wcur) {
    __shared__ uint32_t sAhi[2][32][SWA];
    __shared__ uint32_t sAlo[2][32][SWA];
    __shared__ uint32_t sBhi[2][128][SWA];
    __shared__ uint32_t sBlo[2][128][SWA];

    const int tid  = threadIdx.x;
    const int lane = tid & 31, wid = tid >> 5;
    const int wn = wid;                      // 1 x 8 warp grid; warp tile m32 x n16
    const int tile = blockIdx.x;
    const int ldW = NCH * 16;                // W row stride in packed u32

    float acc[2][2][4];
#pragma unroll
    for (int mi = 0; mi < 2; mi++)
#pragma unroll
        for (int ni = 0; ni < 2; ni++)
#pragma unroll
            for (int j = 0; j < 4; j++) acc[mi][ni][j] = 0.f;

    // issue loads for chunk kc into stage s
    auto issue = [&](int kc, int s) {
        // A: 512 u32 per array -> 2 u32 per thread (8B cp)
        {
            int row = tid >> 3, seg = tid & 7;       // seg: 2-u32 units
            uint32_t soff_a = smem_u32p(&sAhi[s][row][seg * 2]);
            uint32_t soff_b = smem_u32p(&sAlo[s][row][seg * 2]);
            int node = tile * 32 + row;
            const uint32_t *ahp, *alp;
            if (MODE == 2) {
                if (kc < 28) {
                    ahp = g_agghi + (size_t)node * 448 + kc * 16 + seg * 2;
                    alp = g_agglo + (size_t)node * 448 + kc * 16 + seg * 2;
                } else {
                    ahp = g_curhi + (size_t)node * 64 + (kc - 28) * 16 + seg * 2;
                    alp = g_curlo + (size_t)node * 64 + (kc - 28) * 16 + seg * 2;
                }
            } else {
                ahp = g_xhi + (size_t)node * 128 + kc * 16 + seg * 2;
                alp = g_xlo + (size_t)node * 128 + kc * 16 + seg * 2;
            }
            cp_async8(soff_a, ahp);
            cp_async8(soff_b, alp);
        }
        // B: 2048 u32 per array -> 2 x 16B per thread
#pragma unroll
        for (int j = 0; j < 2; j++) {
            int i = j * 256 + tid;
            int row = i >> 2, seg = i & 3;           // seg: 4-u32 units
            uint32_t soff_a = smem_u32p(&sBhi[s][row][seg * 4]);
            uint32_t soff_b = smem_u32p(&sBlo[s][row][seg * 4]);
            cp_async16(soff_a, WH + (size_t)row * ldW + kc * 16 + seg * 4);
            cp_async16(soff_b, WL + (size_t)row * ldW + kc * 16 + seg * 4);
        }
        asm volatile("cp.async.commit_group;" ::: "memory");
    };

    issue(0, 0);

    for (int kc = 0; kc < NCH; kc++) {
        int s = kc & 1;
        if (kc + 1 < NCH) {
            issue(kc + 1, s ^ 1);
            asm volatile("cp.async.wait_group 1;" ::: "memory");
        } else {
            asm volatile("cp.async.wait_group 0;" ::: "memory");
        }
        __syncthreads();

        // ---- compute: 2 ksteps of k16 on stage s ----
#pragma unroll
        for (int ks = 0; ks < 2; ks++) {
            int c0 = ks * 8 + (lane & 3);
            int c1 = c0 + 4;
            uint32_t ah[2][4], al[2][4], bh[2][2], bl[2][2];
#pragma unroll
            for (int mi = 0; mi < 2; mi++) {
                int r = mi * 16 + (lane >> 2);
                ah[mi][0] = sAhi[s][r][c0];     ah[mi][1] = sAhi[s][r + 8][c0];
                ah[mi][2] = sAhi[s][r][c1];     ah[mi][3] = sAhi[s][r + 8][c1];
                al[mi][0] = sAlo[s][r][c0];     al[mi][1] = sAlo[s][r + 8][c0];
                al[mi][2] = sAlo[s][r][c1];     al[mi][3] = sAlo[s][r + 8][c1];
            }
#pragma unroll
            for (int ni = 0; ni < 2; ni++) {
                int fr = wn * 16 + ni * 8 + (lane >> 2);
                bh[ni][0] = sBhi[s][fr][c0];    bh[ni][1] = sBhi[s][fr][c1];
                bl[ni][0] = sBlo[s][fr][c0];    bl[ni][1] = sBlo[s][fr][c1];
            }
#pragma unroll
            for (int mi = 0; mi < 2; mi++)
#pragma unroll
                for (int ni = 0; ni < 2; ni++) {
                    mma16816(acc[mi][ni], ah[mi], bh[ni]);
                    mma16816(acc[mi][ni], al[mi], bh[ni]);
                    mma16816(acc[mi][ni], ah[mi], bl[ni]);
                }
        }
        __syncthreads();   // stage s free for issue(kc+2, s)
    }

    // ---- epilogue ----
    float t0 = __ldg(tempP);
#pragma unroll
    for (int mi = 0; mi < 2; mi++) {
#pragma unroll
        for (int ni = 0; ni < 2; ni++) {
            int row = tile * 32 + mi * 16 + (lane >> 2);
            int col = wn * 16 + ni * 8 + (lane & 3) * 2;
            float* a4 = acc[mi][ni];
            float b0 = bias[col], b1 = bias[col + 1];
#pragma unroll
            for (int half = 0; half < 2; half++) {
                int rr = row + half * 8;
                float vx = a4[half * 2 + 0] + b0;
                float vy = a4[half * 2 + 1] + b1;
                if (MODE == 1) {
                    vx *= t0; vy *= t0;
                    *(float2*)&g_hidden[(size_t)rr * 128 + col] = make_float2(vx, vy);
                } else {
                    if (relu) { vx = fmaxf(vx, 0.f); vy = fmaxf(vy, 0.f); }
                    float2 h = *(float2*)&g_hidden[(size_t)rr * 128 + col];
                    h.x = fmaf(t0, vx, h.x);
                    h.y = fmaf(t0, vy, h.y);
                    *(float2*)&g_hidden[(size_t)rr * 128 + col] = h;
                }
                if (MODE == 1 || wcur) {
                    *(float2*)&g_cur[(size_t)rr * 128 + col] = make_float2(vx, vy);
                    uint32_t h_, l_;
                    split2(vx, vy, h_, l_);
                    g_curhi[(size_t)rr * 64 + (col >> 1)] = h_;
                    g_curlo[(size_t)rr * 64 + (col >> 1)] = l_;
                }
            }
        }
    }
}

// ---------------- lin2 ----------------
__global__ void lin2_kernel(const float* __restrict__ W, const float* __restrict__ B,
                            float* __restrict__ out, int M) {
    int t = blockIdx.x * blockDim.x + threadIdx.x;
    int rowi = t >> 5, lane = t & 31;
    if (rowi >= M) return;
    float4 h = ((const float4*)g_hidden)[(size_t)rowi * 32 + lane];
    int k = lane * 4;
    float a0 = h.x * W[k * 2]     + h.y * W[(k + 1) * 2]     + h.z * W[(k + 2) * 2]     + h.w * W[(k + 3) * 2];
    float a1 = h.x * W[k * 2 + 1] + h.y * W[(k + 1) * 2 + 1] + h.z * W[(k + 2) * 2 + 1] + h.w * W[(k + 3) * 2 + 1];
#pragma unroll
    for (int o = 16; o > 0; o >>= 1) {
        a0 += __shfl_down_sync(0xffffffff, a0, o);
        a1 += __shfl_down_sync(0xffffffff, a1, o);
    }
    if (lane == 0) {
        out[rowi * 2]     = a0 + B[0];
        out[rowi * 2 + 1] = a1 + B[1];
    }
}

// ---------------- launch ----------------
extern "C" void kernel_launch(void* const* d_in, const int* in_sizes, int n_in,
                              void* d_out, int out_size) {
    const float* x     = (const float*)d_in[0];
    const int*   ei    = (const int*)d_in[1];
    const int*   et    = (const int*)d_in[2];
    const float* temp  = (const float*)d_in[3];
    const float* l1w   = (const float*)d_in[4];
    const float* l1b   = (const float*)d_in[5];
    const float* l2w   = (const float*)d_in[6];
    const float* l2b   = (const float*)d_in[7];
    const float* comps = (const float*)d_in[8];
    const float* bases = (const float*)d_in[9];
    const float* roots = (const float*)d_in[10];
    const float* cbias = (const float*)d_in[11];
    float* out = (float*)d_out;

    const int E = in_sizes[2];
    const int M = in_sizes[0] / INC;
    const int* src = ei;
    const int* dst = ei + E;

    uint32_t* whi_ptr;  cudaGetSymbolAddress((void**)&whi_ptr, g_whi);
    uint32_t* wlo_ptr;  cudaGetSymbolAddress((void**)&wlo_ptr, g_wlo);
    uint32_t* l1hi_ptr; cudaGetSymbolAddress((void**)&l1hi_ptr, g_l1hi);
    uint32_t* l1lo_ptr; cudaGetSymbolAddress((void**)&l1lo_ptr, g_l1lo);

    // static side stream + events (created on first, uncaptured, call)
    static cudaStream_t s2 = nullptr;
    static cudaEvent_t evF = nullptr, evJ = nullptr;
    if (s2 == nullptr) {
        cudaStreamCreateWithFlags(&s2, cudaStreamNonBlocking);
        cudaEventCreateWithFlags(&evF, cudaEventDisableTiming);
        cudaEventCreateWithFlags(&evJ, cudaEventDisableTiming);
    }

    // fork: sort chain on s2, weight/x prep + lin1 on default stream
    cudaEventRecord(evF, 0);
    cudaStreamWaitEvent(s2, evF, 0);

    zero_cnt_kernel<<<(NBINS + 255) / 256, 256, 0, s2>>>();
    count_kernel<<<(E + 255) / 256, 256, 0, s2>>>(dst, et, E);
    scan1_kernel<<<NBINS / 1024, 1024, 0, s2>>>();
    scan2_kernel<<<1, 512, 0, s2>>>();
    scan3_kernel<<<(NBINS + 255) / 256, 256, 0, s2>>>();
    sort_kernel<<<(E + 255) / 256, 256, 0, s2>>>(src, dst, et, E);

    conv_w_kernel<<<(LAYERS * 128 * 512 + 255) / 256, 256>>>(comps, bases, roots);
    l1_w_kernel<<<(128 * 128 + 255) / 256, 256>>>(l1w);
    xsplit_kernel<<<(NPAD * 128 + 255) / 256, 256>>>(x, M);
    // lin1: hidden = cur = temp0*(x@W1 + b1)
    gemm_mma<8, 1><<<NPADT, 256>>>(l1hi_ptr, l1lo_ptr, l1b, temp, 0, 0);

    // join
    cudaEventRecord(evJ, s2);
    cudaStreamWaitEvent(0, evJ, 0);

    // conv layers: agg (high-occupancy) then GEMM (pipelined, occ 3)
    for (int l = 0; l < LAYERS; l++) {
        agg_kernel<<<(M * 32 + 255) / 256, 256>>>(M);
        gemm_mma<32, 2><<<NPADT, 256>>>(
            whi_ptr + (size_t)l * 128 * 512, wlo_ptr + (size_t)l * 128 * 512,
            cbias + l * HIDC, temp + l + 1,
            (l < LAYERS - 1) ? 1 : 0, (l < LAYERS - 1) ? 1 : 0);
    }

    lin2_kernel<<<(M * 32 + 255) / 256, 256>>>(l2w, l2b, out, M);
}

// round 17
// speedup vs baseline: 1.2315x; 1.2315x over previous
#include <cuda_runtime.h>
#include <cstdint>

#define NN      50000
#define NPADT   1564           /* 32-row tiles: 50048/32 */
#define NPAD    (NPADT*32)     /* 50048 */
#define HIDC    128
#define INC     256
#define LAYERS  3
#define NBINS   (NPAD*8)       /* 400384 */
#define EMAX    600000
#define SW      36             /* smem row width in u32 (32 data + 4 pad) */

// ---------------- device scratch (static globals; no allocation) ----------------
__device__ __align__(16) float    g_hidden[(size_t)NPAD * 128];
__device__ __align__(16) float    g_cur[(size_t)NPAD * 128];       // fp32 for agg gather
__device__ __align__(16) uint32_t g_curhi[(size_t)NPAD * 64];      // packed bf16x2
__device__ __align__(16) uint32_t g_curlo[(size_t)NPAD * 64];
__device__ __align__(16) uint32_t g_agghi[(size_t)NPAD * 448];     // 896 k -> 448 pairs
__device__ __align__(16) uint32_t g_agglo[(size_t)NPAD * 448];
__device__ __align__(16) uint32_t g_xhi[(size_t)NPAD * 128];       // x pre-split (256 k)
__device__ __align__(16) uint32_t g_xlo[(size_t)NPAD * 128];
__device__ __align__(16) uint32_t g_whi[LAYERS * 128 * 512];       // [l][f][pc]
__device__ __align__(16) uint32_t g_wlo[LAYERS * 128 * 512];
__device__ __align__(16) uint32_t g_l1hi[128 * 128];               // [f][pc]
__device__ __align__(16) uint32_t g_l1lo[128 * 128];
__device__ int g_cnt[NBINS];
__device__ int g_off[NBINS];
__device__ int g_cursor[NBINS];
__device__ int g_bsum[NBINS / 1024];
__device__ int g_bsumx[NBINS / 1024];
__device__ int g_esrc[EMAX];

// ---------------- helpers ----------------
__device__ __forceinline__ uint32_t smem_u32p(const void* p) {
    uint32_t a;
    asm("{ .reg .u64 t; cvta.to.shared.u64 t, %1; cvt.u32.u64 %0, t; }" : "=r"(a) : "l"(p));
    return a;
}
__device__ __forceinline__ void cp_async16(uint32_t saddr, const void* g) {
    asm volatile("cp.async.ca.shared.global [%0], [%1], 16;" :: "r"(saddr), "l"(g));
}
__device__ __forceinline__ uint32_t pack2(float x, float y) {
    uint32_t r;
    asm("cvt.rn.bf16x2.f32 %0, %1, %2;" : "=r"(r) : "f"(y), "f"(x));
    return r;
}
__device__ __forceinline__ void split2(float x, float y, uint32_t& hi, uint32_t& lo) {
    hi = pack2(x, y);
    float fx = __uint_as_float(hi << 16);
    float fy = __uint_as_float(hi & 0xFFFF0000u);
    lo = pack2(x - fx, y - fy);
}
__device__ __forceinline__ void mma16816(float* d, const uint32_t* a, const uint32_t* b) {
    asm volatile(
        "mma.sync.aligned.m16n8k16.row.col.f32.bf16.bf16.f32 "
        "{%0,%1,%2,%3}, {%4,%5,%6,%7}, {%8,%9}, {%0,%1,%2,%3};"
        : "+f"(d[0]), "+f"(d[1]), "+f"(d[2]), "+f"(d[3])
        : "r"(a[0]), "r"(a[1]), "r"(a[2]), "r"(a[3]), "r"(b[0]), "r"(b[1]));
}

// ---------------- prep: conv weights packed bf16 hi/lo: [l][f][pc], k=2pc ----------
__global__ void conv_w_kernel(const float* __restrict__ comps,
                              const float* __restrict__ bases,
                              const float* __restrict__ roots) {
    int idx = blockIdx.x * blockDim.x + threadIdx.x;
    if (idx >= LAYERS * 128 * 512) return;
    int l   = idx / (128 * 512);
    int rem = idx % (128 * 512);
    int f   = rem >> 9;
    int pc  = rem & 511;
    int k0  = pc * 2;
    int r   = k0 >> 7, d = k0 & 127;
    float v0, v1;
    if (r < 7) {
        v0 = 0.f; v1 = 0.f;
#pragma unroll
        for (int b = 0; b < 8; b++) {
            float c = comps[l * 56 + r * 8 + b];
            const float* bb = bases + ((size_t)(l * 8 + b) * 128 + d) * 128 + f;
            v0 += c * bb[0];
            v1 += c * bb[128];
        }
    } else {
        const float* rr = roots + ((size_t)l * 128 + d) * 128 + f;
        v0 = rr[0];
        v1 = rr[128];
    }
    uint32_t hi, lo;
    split2(v0, v1, hi, lo);
    g_whi[idx] = hi;
    g_wlo[idx] = lo;
}

__global__ void l1_w_kernel(const float* __restrict__ w) {
    int idx = blockIdx.x * blockDim.x + threadIdx.x;
    if (idx >= 128 * 128) return;
    int f = idx >> 7, pc = idx & 127;
    int k0 = pc * 2;
    uint32_t hi, lo;
    split2(w[k0 * 128 + f], w[(k0 + 1) * 128 + f], hi, lo);
    g_l1hi[idx] = hi;
    g_l1lo[idx] = lo;
}

// ---------------- prep: x pre-split packed [node][128 pc] ----------------
__global__ void xsplit_kernel(const float* __restrict__ x, int M) {
    int idx = blockIdx.x * blockDim.x + threadIdx.x;
    if (idx >= NPAD * 128) return;
    int node = idx >> 7, pc = idx & 127;
    int k0 = pc * 2;
    float v0 = 0.f, v1 = 0.f;
    if (node < M) {
        v0 = x[(size_t)node * INC + k0];
        v1 = x[(size_t)node * INC + k0 + 1];
    }
    uint32_t hi, lo;
    split2(v0, v1, hi, lo);
    g_xhi[idx] = hi;
    g_xlo[idx] = lo;
}

// ---------------- counts / scan / sort ----------------
__global__ void zero_cnt_kernel() {
    int i = blockIdx.x * blockDim.x + threadIdx.x;
    if (i < NBINS) g_cnt[i] = 0;
}
__global__ void count_kernel(const int* __restrict__ dst, const int* __restrict__ et, int E) {
    int e = blockIdx.x * blockDim.x + threadIdx.x;
    if (e < E) atomicAdd(&g_cnt[dst[e] * 8 + et[e]], 1);
}
__global__ void scan1_kernel() {
    __shared__ int s[1024];
    int tid = threadIdx.x;
    int i   = blockIdx.x * 1024 + tid;
    int v   = g_cnt[i];
    s[tid] = v;
    __syncthreads();
#pragma unroll
    for (int o = 1; o < 1024; o <<= 1) {
        int t = (tid >= o) ? s[tid - o] : 0;
        __syncthreads();
        s[tid] += t;
        __syncthreads();
    }
    g_off[i] = s[tid] - v;
    if (tid == 1023) g_bsum[blockIdx.x] = s[1023];
}
__global__ void scan2_kernel() {
    __shared__ int s[512];
    int tid = threadIdx.x;
    int v = (tid < NBINS / 1024) ? g_bsum[tid] : 0;
    s[tid] = v;
    __syncthreads();
#pragma unroll
    for (int o = 1; o < 512; o <<= 1) {
        int t = (tid >= o) ? s[tid - o] : 0;
        __syncthreads();
        s[tid] += t;
        __syncthreads();
    }
    if (tid < NBINS / 1024) g_bsumx[tid] = s[tid] - v;
}
__global__ void scan3_kernel() {
    int i = blockIdx.x * blockDim.x + threadIdx.x;
    if (i >= NBINS) return;
    int o = g_off[i] + g_bsumx[i >> 10];
    g_off[i] = o;
    g_cursor[i] = o;
}
__global__ void sort_kernel(const int* __restrict__ src, const int* __restrict__ dst,
                            const int* __restrict__ et, int E) {
    int e = blockIdx.x * blockDim.x + threadIdx.x;
    if (e >= E) return;
    int key = dst[e] * 8 + et[e];
    int pos = atomicAdd(&g_cursor[key], 1);
    g_esrc[pos] = src[e];
}

// ---------------- aggregation (R10: warp per node, 7 descs preloaded) ----------
__global__ void agg_kernel(int M) {
    int t = blockIdx.x * blockDim.x + threadIdx.x;
    int d = t >> 5, lane = t & 31;
    if (d >= M) return;
    const float4* cur4 = (const float4*)g_cur;
    int st[7], n[7];
#pragma unroll
    for (int r = 0; r < 7; r++) {
        st[r] = __ldg(&g_off[d * 8 + r]);
        n[r]  = __ldg(&g_cnt[d * 8 + r]);
    }
#pragma unroll
    for (int r = 0; r < 7; r++) {
        float4 acc = make_float4(0.f, 0.f, 0.f, 0.f);
        for (int i = 0; i < n[r]; i++) {
            int s = __ldg(&g_esrc[st[r] + i]);
            float4 v = cur4[(size_t)s * 32 + lane];
            acc.x += v.x; acc.y += v.y; acc.z += v.z; acc.w += v.w;
        }
        float s = 1.f / fmaxf((float)n[r], 1.f);
        uint32_t h0, l0, h1, l1;
        split2(acc.x * s, acc.y * s, h0, l0);
        split2(acc.z * s, acc.w * s, h1, l1);
        size_t base = (size_t)d * 448 + r * 64;
        ((uint2*)(g_agghi + base))[lane] = make_uint2(h0, h1);
        ((uint2*)(g_agglo + base))[lane] = make_uint2(l0, l1);
    }
}

// ---------------- bf16x3 GEMM: 32x128 tile, K-tile 64, cp.async, 3 CTA/SM ---------
// warp grid 1x8, warp tile m32 x n16, acc[2][2][4] = 16 regs/thread.
// MODE 1: lin1  NCH=4, A from g_xhi/g_xlo.       hidden=cur=(acc+b)*t0 (+packed cur)
// MODE 2: conv  NCH=16, kc<14 from g_agghi/lo, kc>=14 from g_curhi/lo (own rows).
//               v=acc+b; relu?; hidden+=t0*v; wcur? cur=v (fp32 + packed)
template <int NCH, int MODE>
__global__ void __launch_bounds__(256, 3) gemm_mma(
    const uint32_t* __restrict__ WH,
    const uint32_t* __restrict__ WL,
    const float* __restrict__ bias,
    const float* __restrict__ tempP,
    int relu, int wcur) {
    __shared__ uint32_t sAhi[32][SW];
    __shared__ uint32_t sAlo[32][SW];
    __shared__ uint32_t sBhi[128][SW];
    __shared__ uint32_t sBlo[128][SW];

    const int tid  = threadIdx.x;
    const int lane = tid & 31, wid = tid >> 5;
    const int wn = wid;                      // 1 x 8 warp grid; warp tile m32 x n16
    const int tile = blockIdx.x;
    const int ldW = NCH * 32;                // W row stride in packed u32

    const uint32_t sa_hi = smem_u32p(&sAhi[0][0]);
    const uint32_t sa_lo = smem_u32p(&sAlo[0][0]);
    const uint32_t sb_hi = smem_u32p(&sBhi[0][0]);
    const uint32_t sb_lo = smem_u32p(&sBlo[0][0]);

    float acc[2][2][4];
#pragma unroll
    for (int mi = 0; mi < 2; mi++)
#pragma unroll
        for (int ni = 0; ni < 2; ni++)
#pragma unroll
            for (int j = 0; j < 4; j++) acc[mi][ni][j] = 0.f;

    for (int kc = 0; kc < NCH; kc++) {
        // ---- A: 32 rows x 8 segs = 256 -> 1 cp per thread per array ----
        {
            int row = tid >> 3, seg = tid & 7;
            uint32_t soff = (uint32_t)(row * SW + seg * 4) * 4;
            int node = tile * 32 + row;
            const uint32_t *ahp, *alp;
            if (MODE == 2) {
                if (kc < 14) {
                    ahp = g_agghi + (size_t)node * 448 + kc * 32 + seg * 4;
                    alp = g_agglo + (size_t)node * 448 + kc * 32 + seg * 4;
                } else {
                    ahp = g_curhi + (size_t)node * 64 + (kc - 14) * 32 + seg * 4;
                    alp = g_curlo + (size_t)node * 64 + (kc - 14) * 32 + seg * 4;
                }
            } else {
                ahp = g_xhi + (size_t)node * 128 + kc * 32 + seg * 4;
                alp = g_xlo + (size_t)node * 128 + kc * 32 + seg * 4;
            }
            cp_async16(sa_hi + soff, ahp);
            cp_async16(sa_lo + soff, alp);
        }
        // ---- B: 128 rows x 8 segs = 1024 -> 4 cp per thread per array ----
#pragma unroll
        for (int j = 0; j < 4; j++) {
            int i = j * 256 + tid;
            int row = i >> 3, seg = i & 7;
            uint32_t soff = (uint32_t)(row * SW + seg * 4) * 4;
            cp_async16(sb_hi + soff, WH + (size_t)row * ldW + kc * 32 + seg * 4);
            cp_async16(sb_lo + soff, WL + (size_t)row * ldW + kc * 32 + seg * 4);
        }
        asm volatile("cp.async.commit_group;" ::: "memory");
        asm volatile("cp.async.wait_group 0;" ::: "memory");
        __syncthreads();

        // ---- inner: 4 ksteps of k16 ----
#pragma unroll
        for (int ks = 0; ks < 4; ks++) {
            int c0 = ks * 8 + (lane & 3);
            int c1 = c0 + 4;
            uint32_t ah[2][4], al[2][4], bh[2][2], bl[2][2];
#pragma unroll
            for (int mi = 0; mi < 2; mi++) {
                int r = mi * 16 + (lane >> 2);
                ah[mi][0] = sAhi[r][c0];     ah[mi][1] = sAhi[r + 8][c0];
                ah[mi][2] = sAhi[r][c1];     ah[mi][3] = sAhi[r + 8][c1];
                al[mi][0] = sAlo[r][c0];     al[mi][1] = sAlo[r + 8][c0];
                al[mi][2] = sAlo[r][c1];     al[mi][3] = sAlo[r + 8][c1];
            }
#pragma unroll
            for (int ni = 0; ni < 2; ni++) {
                int fr = wn * 16 + ni * 8 + (lane >> 2);
                bh[ni][0] = sBhi[fr][c0];    bh[ni][1] = sBhi[fr][c1];
                bl[ni][0] = sBlo[fr][c0];    bl[ni][1] = sBlo[fr][c1];
            }
#pragma unroll
            for (int mi = 0; mi < 2; mi++)
#pragma unroll
                for (int ni = 0; ni < 2; ni++) {
                    mma16816(acc[mi][ni], ah[mi], bh[ni]);
                    mma16816(acc[mi][ni], al[mi], bh[ni]);
                    mma16816(acc[mi][ni], ah[mi], bl[ni]);
                }
        }
        __syncthreads();
    }

    // ---- epilogue ----
    float t0 = __ldg(tempP);
#pragma unroll
    for (int mi = 0; mi < 2; mi++) {
#pragma unroll
        for (int ni = 0; ni < 2; ni++) {
            int row = tile * 32 + mi * 16 + (lane >> 2);
            int col = wn * 16 + ni * 8 + (lane & 3) * 2;
            float* a4 = acc[mi][ni];
            float b0 = bias[col], b1 = bias[col + 1];
#pragma unroll
            for (int half = 0; half < 2; half++) {
                int rr = row + half * 8;
                float vx = a4[half * 2 + 0] + b0;
                float vy = a4[half * 2 + 1] + b1;
                if (MODE == 1) {
                    vx *= t0; vy *= t0;
                    *(float2*)&g_hidden[(size_t)rr * 128 + col] = make_float2(vx, vy);
                } else {
                    if (relu) { vx = fmaxf(vx, 0.f); vy = fmaxf(vy, 0.f); }
                    float2 h = *(float2*)&g_hidden[(size_t)rr * 128 + col];
                    h.x = fmaf(t0, vx, h.x);
                    h.y = fmaf(t0, vy, h.y);
                    *(float2*)&g_hidden[(size_t)rr * 128 + col] = h;
                }
                if (MODE == 1 || wcur) {
                    *(float2*)&g_cur[(size_t)rr * 128 + col] = make_float2(vx, vy);
                    uint32_t h_, l_;
                    split2(vx, vy, h_, l_);
                    g_curhi[(size_t)rr * 64 + (col >> 1)] = h_;
                    g_curlo[(size_t)rr * 64 + (col >> 1)] = l_;
                }
            }
        }
    }
}

// ---------------- lin2 ----------------
__global__ void lin2_kernel(const float* __restrict__ W, const float* __restrict__ B,
                            float* __restrict__ out, int M) {
    int t = blockIdx.x * blockDim.x + threadIdx.x;
    int rowi = t >> 5, lane = t & 31;
    if (rowi >= M) return;
    float4 h = ((const float4*)g_hidden)[(size_t)rowi * 32 + lane];
    int k = lane * 4;
    float a0 = h.x * W[k * 2]     + h.y * W[(k + 1) * 2]     + h.z * W[(k + 2) * 2]     + h.w * W[(k + 3) * 2];
    float a1 = h.x * W[k * 2 + 1] + h.y * W[(k + 1) * 2 + 1] + h.z * W[(k + 2) * 2 + 1] + h.w * W[(k + 3) * 2 + 1];
#pragma unroll
    for (int o = 16; o > 0; o >>= 1) {
        a0 += __shfl_down_sync(0xffffffff, a0, o);
        a1 += __shfl_down_sync(0xffffffff, a1, o);
    }
    if (lane == 0) {
        out[rowi * 2]     = a0 + B[0];
        out[rowi * 2 + 1] = a1 + B[1];
    }
}

// ---------------- launch ----------------
extern "C" void kernel_launch(void* const* d_in, const int* in_sizes, int n_in,
                              void* d_out, int out_size) {
    const float* x     = (const float*)d_in[0];
    const int*   ei    = (const int*)d_in[1];
    const int*   et    = (const int*)d_in[2];
    const float* temp  = (const float*)d_in[3];
    const float* l1w   = (const float*)d_in[4];
    const float* l1b   = (const float*)d_in[5];
    const float* l2w   = (const float*)d_in[6];
    const float* l2b   = (const float*)d_in[7];
    const float* comps = (const float*)d_in[8];
    const float* bases = (const float*)d_in[9];
    const float* roots = (const float*)d_in[10];
    const float* cbias = (const float*)d_in[11];
    float* out = (float*)d_out;

    const int E = in_sizes[2];
    const int M = in_sizes[0] / INC;
    const int* src = ei;
    const int* dst = ei + E;

    uint32_t* whi_ptr;  cudaGetSymbolAddress((void**)&whi_ptr, g_whi);
    uint32_t* wlo_ptr;  cudaGetSymbolAddress((void**)&wlo_ptr, g_wlo);
    uint32_t* l1hi_ptr; cudaGetSymbolAddress((void**)&l1hi_ptr, g_l1hi);
    uint32_t* l1lo_ptr; cudaGetSymbolAddress((void**)&l1lo_ptr, g_l1lo);

    // static side stream + events (created on first, uncaptured, call)
    static cudaStream_t s2 = nullptr;
    static cudaEvent_t evF = nullptr, evJ = nullptr;
    if (s2 == nullptr) {
        cudaStreamCreateWithFlags(&s2, cudaStreamNonBlocking);
        cudaEventCreateWithFlags(&evF, cudaEventDisableTiming);
        cudaEventCreateWithFlags(&evJ, cudaEventDisableTiming);
    }

    // fork: sort chain on s2, weight/x prep + lin1 on default stream
    cudaEventRecord(evF, 0);
    cudaStreamWaitEvent(s2, evF, 0);

    zero_cnt_kernel<<<(NBINS + 255) / 256, 256, 0, s2>>>();
    count_kernel<<<(E + 255) / 256, 256, 0, s2>>>(dst, et, E);
    scan1_kernel<<<NBINS / 1024, 1024, 0, s2>>>();
    scan2_kernel<<<1, 512, 0, s2>>>();
    scan3_kernel<<<(NBINS + 255) / 256, 256, 0, s2>>>();
    sort_kernel<<<(E + 255) / 256, 256, 0, s2>>>(src, dst, et, E);

    conv_w_kernel<<<(LAYERS * 128 * 512 + 255) / 256, 256>>>(comps, bases, roots);
    l1_w_kernel<<<(128 * 128 + 255) / 256, 256>>>(l1w);
    xsplit_kernel<<<(NPAD * 128 + 255) / 256, 256>>>(x, M);
    // lin1: hidden = cur = temp0*(x@W1 + b1)
    gemm_mma<4, 1><<<NPADT, 256>>>(l1hi_ptr, l1lo_ptr, l1b, temp, 0, 0);

    // join
    cudaEventRecord(evJ, s2);
    cudaStreamWaitEvent(0, evJ, 0);

    // conv layers: agg (high-occupancy) then GEMM (32-row tiles, occ 3)
    for (int l = 0; l < LAYERS; l++) {
        agg_kernel<<<(M * 32 + 255) / 256, 256>>>(M);
        gemm_mma<16, 2><<<NPADT, 256>>>(
            whi_ptr + (size_t)l * 128 * 512, wlo_ptr + (size_t)l * 128 * 512,
            cbias + l * HIDC, temp + l + 1,
            (l < LAYERS - 1) ? 1 : 0, (l < LAYERS - 1) ? 1 : 0);
    }

    lin2_kernel<<<(M * 32 + 255) / 256, 256>>>(l2w, l2b, out, M);
}